// round 12
// baseline (speedup 1.0000x reference)
#include <cuda_runtime.h>
#include <cstdint>

#define NN 50000
#define EE 800000
#define FF 128
#define LL 3
#define GG 256
#define TT 10

#define BRF 128
#define APITCH 36
#define WPITCH 132

// row chunks for gather/gemm overlap: 148/148/95 CTAs of 128 rows
#define C0 18944
#define C1 18944
#define C2 (NN - C0 - C1)   // 12112

// ---- scratch (device globals; no allocation allowed) ----
__device__ float g_agg[NN * FF];
__device__ float g_f1[NN * FF];
__device__ float g_f2[NN * FF];
__device__ float g_f3[NN * FF];
__device__ float g_WlT[LL * FF * FF];
__device__ float g_WrT[LL * FF * FF];
__device__ float g_W1T[LL * FF * FF];
__device__ float g_pool[GG * LL * FF];
__device__ float g_z[GG * FF];
__device__ int   g_start[GG + 1];
__device__ int   g_src[EE];
__device__ int   g_dst[EE];
__device__ int   g_csr[EE];
__device__ int   g_rowptr[NN + 1];
__device__ int   g_indeg[NN];
__device__ int   g_cursor[NN];
__device__ int   g_idx64;

// ---- weight pre-transpose: Wl/Wr [l][o][k] -> [l][k][o]; W1 [c][j] -> [j][c] ----
__global__ void gs_transpose_kernel(const float* __restrict__ Wl,
                                    const float* __restrict__ Wr,
                                    const float* __restrict__ W1) {
    int idx = blockIdx.x * blockDim.x + threadIdx.x;
    if (idx < LL * FF * FF) {
        int l = idx / (FF * FF), r = idx % (FF * FF);
        int o = r / FF, k = r % FF;
        g_WlT[l * FF * FF + k * FF + o] = Wl[idx];
        g_WrT[l * FF * FF + k * FF + o] = Wr[idx];
        int c = idx / (LL * FF), j = idx % (LL * FF);
        g_W1T[j * FF + c] = W1[idx];
    }
}

__global__ void gs_zero_idx_kernel() {
    int i = blockIdx.x * blockDim.x + threadIdx.x;
    if (i < NN) g_indeg[i] = 0;
}

// ---- dtype detection (parallel): int64 edge_index has all-zero high words ----
__global__ void gs_detect_kernel(const int* __restrict__ ei32) {
    __shared__ int flag;
    if (threadIdx.x == 0) flag = 1;
    __syncthreads();
    if (ei32[2 * threadIdx.x + 1] != 0) flag = 0;
    __syncthreads();
    if (threadIdx.x == 0) g_idx64 = flag;
}

__global__ void gs_convert_count_kernel(const void* __restrict__ ei) {
    int e = blockIdx.x * blockDim.x + threadIdx.x;
    if (e >= EE) return;
    int s, d;
    if (g_idx64) {
        const long long* p = (const long long*)ei;
        s = (int)p[e]; d = (int)p[EE + e];
    } else {
        const int* p = (const int*)ei;
        s = p[e]; d = p[EE + e];
    }
    g_src[e] = s; g_dst[e] = d;
    atomicAdd(&g_indeg[d], 1);
}

__global__ void gs_scan_kernel() {
    __shared__ int ssum[1024];
    const int t = threadIdx.x;
    const int CH = (NN + 1023) / 1024;
    const int base = t * CH;
    int s = 0;
    for (int i = 0; i < CH; i++) {
        int idx = base + i;
        if (idx < NN) s += g_indeg[idx];
    }
    ssum[t] = s;
    __syncthreads();
    for (int off = 1; off < 1024; off <<= 1) {
        int v = (t >= off) ? ssum[t - off] : 0;
        __syncthreads();
        ssum[t] += v;
        __syncthreads();
    }
    int running = (t == 0) ? 0 : ssum[t - 1];
    for (int i = 0; i < CH; i++) {
        int idx = base + i;
        if (idx < NN) {
            g_rowptr[idx] = running;
            g_cursor[idx] = running;
            running += g_indeg[idx];
        }
    }
    if (t == 1023) g_rowptr[NN] = running;
}

__global__ void gs_fill_kernel() {
    int e = blockIdx.x * blockDim.x + threadIdx.x;
    if (e >= EE) return;
    int pos = atomicAdd(&g_cursor[g_dst[e]], 1);
    g_csr[pos] = g_src[e];
}

__global__ void gs_bounds_kernel(const void* __restrict__ batch) {
    int g = blockIdx.x * blockDim.x + threadIdx.x;
    if (g > GG) return;
    int is64 = g_idx64;
    const long long* b64 = (const long long*)batch;
    const int* b32 = (const int*)batch;
    int lo = 0, hi = NN;
    while (lo < hi) {
        int mid = (lo + hi) >> 1;
        long long v = is64 ? b64[mid] : (long long)b32[mid];
        if (v < (long long)g) lo = mid + 1; else hi = mid;
    }
    g_start[g] = lo;
}

// ---- gather-mean aggregation over a row chunk: one warp per dst node ----
__global__ void __launch_bounds__(256) gs_gather_kernel(const float* __restrict__ h,
                                                        int base, int cnt) {
    int w = (blockIdx.x * blockDim.x + threadIdx.x) >> 5;
    int lane = threadIdx.x & 31;
    if (w >= cnt) return;
    int node = base + w;
    int s0 = g_rowptr[node], s1 = g_rowptr[node + 1];
    float4 acc = make_float4(0.f, 0.f, 0.f, 0.f);
    int j = s0;
    for (; j + 4 <= s1; j += 4) {
        int a = g_csr[j], b = g_csr[j + 1], c = g_csr[j + 2], d = g_csr[j + 3];
        float4 v0 = reinterpret_cast<const float4*>(h + (size_t)a * FF)[lane];
        float4 v1 = reinterpret_cast<const float4*>(h + (size_t)b * FF)[lane];
        float4 v2 = reinterpret_cast<const float4*>(h + (size_t)c * FF)[lane];
        float4 v3 = reinterpret_cast<const float4*>(h + (size_t)d * FF)[lane];
        acc.x += (v0.x + v1.x) + (v2.x + v3.x);
        acc.y += (v0.y + v1.y) + (v2.y + v3.y);
        acc.z += (v0.z + v1.z) + (v2.z + v3.z);
        acc.w += (v0.w + v1.w) + (v2.w + v3.w);
    }
    for (; j < s1; j++) {
        int s = g_csr[j];
        float4 v = reinterpret_cast<const float4*>(h + (size_t)s * FF)[lane];
        acc.x += v.x; acc.y += v.y; acc.z += v.z; acc.w += v.w;
    }
    float iv = (s1 > s0) ? 1.f / (float)(s1 - s0) : 0.f;
    acc.x *= iv; acc.y *= iv; acc.z *= iv; acc.w *= iv;
    reinterpret_cast<float4*>(g_agg + (size_t)node * FF)[lane] = acc;
}

// ---- fused SAGE layer GEMM (512 thr, 128 rows/CTA, chunked by row_base) ----
__global__ void __launch_bounds__(512) gs_gemm_kernel(
    const float* __restrict__ hin,
    const float* __restrict__ WlT, const float* __restrict__ blp,
    const float* __restrict__ WrT, float* __restrict__ hout, int row_base)
{
    extern __shared__ float sm[];
    float* sWl = sm;
    float* sWr = sWl + FF * WPITCH;
    float* sA  = sWr + FF * WPITCH;
    float* sH  = sA + BRF * APITCH;
    const int t = threadIdx.x;
    const int row0 = row_base + blockIdx.x * BRF;

    for (int i = t; i < FF * FF / 4; i += 512) {
        int k = i >> 5, c4 = i & 31;
        float4 wl = reinterpret_cast<const float4*>(WlT)[i];
        float4 wr = reinterpret_cast<const float4*>(WrT)[i];
        reinterpret_cast<float4*>(sWl + k * WPITCH)[c4] = wl;
        reinterpret_cast<float4*>(sWr + k * WPITCH)[c4] = wr;
    }

    const int tc = t & 15, tr = t >> 4;
    const int cA = tc * 4, cB = 64 + tc * 4, r0 = tr * 4;

    float acc[4][8];
#pragma unroll
    for (int i = 0; i < 4; i++)
#pragma unroll
        for (int j = 0; j < 8; j++) acc[i][j] = 0.f;

    for (int kc = 0; kc < FF; kc += 32) {
        __syncthreads();
        for (int i = t; i < BRF * 8; i += 512) {
            int r = i >> 3, k4 = i & 7;
            int gr = row0 + r; if (gr >= NN) gr = NN - 1;
            reinterpret_cast<float4*>(sA + r * APITCH)[k4] =
                reinterpret_cast<const float4*>(g_agg + (size_t)gr * FF + kc)[k4];
            reinterpret_cast<float4*>(sH + r * APITCH)[k4] =
                reinterpret_cast<const float4*>(hin + (size_t)gr * FF + kc)[k4];
        }
        __syncthreads();
#pragma unroll
        for (int k = 0; k < 32; k++) {
            const float* wrow_l = sWl + (kc + k) * WPITCH;
            const float* wrow_r = sWr + (kc + k) * WPITCH;
            float4 wl0 = *reinterpret_cast<const float4*>(wrow_l + cA);
            float4 wl1 = *reinterpret_cast<const float4*>(wrow_l + cB);
            float4 wr0 = *reinterpret_cast<const float4*>(wrow_r + cA);
            float4 wr1 = *reinterpret_cast<const float4*>(wrow_r + cB);
#pragma unroll
            for (int i = 0; i < 4; i++) {
                float a = sA[(r0 + i) * APITCH + k];
                float h = sH[(r0 + i) * APITCH + k];
                acc[i][0] += a * wl0.x + h * wr0.x;
                acc[i][1] += a * wl0.y + h * wr0.y;
                acc[i][2] += a * wl0.z + h * wr0.z;
                acc[i][3] += a * wl0.w + h * wr0.w;
                acc[i][4] += a * wl1.x + h * wr1.x;
                acc[i][5] += a * wl1.y + h * wr1.y;
                acc[i][6] += a * wl1.z + h * wr1.z;
                acc[i][7] += a * wl1.w + h * wr1.w;
            }
        }
    }

    float4 b0 = *reinterpret_cast<const float4*>(blp + cA);
    float4 b1v = *reinterpret_cast<const float4*>(blp + cB);
#pragma unroll
    for (int i = 0; i < 4; i++) {
        int gr = row0 + r0 + i;
        if (gr < NN) {
            float4 o0 = make_float4(acc[i][0] + b0.x, acc[i][1] + b0.y,
                                    acc[i][2] + b0.z, acc[i][3] + b0.w);
            float4 o1 = make_float4(acc[i][4] + b1v.x, acc[i][5] + b1v.y,
                                    acc[i][6] + b1v.z, acc[i][7] + b1v.w);
            *reinterpret_cast<float4*>(hout + (size_t)gr * FF + cA) = o0;
            *reinterpret_cast<float4*>(hout + (size_t)gr * FF + cB) = o1;
        }
    }
}

__global__ void gs_pool_kernel() {
    int g = blockIdx.x;
    int s = g_start[g], e = g_start[g + 1];
    int t = threadIdx.x;
    int l = t >> 7, c = t & 127;
    const float* f = (l == 0) ? g_f1 : (l == 1) ? g_f2 : g_f3;
    float m = -3.402823466e38f;
    int i = s;
    for (; i + 4 <= e; i += 4) {
        float v0 = f[(size_t)(i + 0) * FF + c];
        float v1 = f[(size_t)(i + 1) * FF + c];
        float v2 = f[(size_t)(i + 2) * FF + c];
        float v3 = f[(size_t)(i + 3) * FF + c];
        m = fmaxf(m, fmaxf(fmaxf(v0, v1), fmaxf(v2, v3)));
    }
    for (; i < e; i++) m = fmaxf(m, f[(size_t)i * FF + c]);
    g_pool[g * (LL * FF) + t] = m;
}

__global__ void gs_mlp1_kernel(const float* __restrict__ b1) {
    __shared__ float sp[LL * FF];
    int g = blockIdx.x, t = threadIdx.x;
    for (int i = t; i < LL * FF; i += FF) sp[i] = g_pool[g * (LL * FF) + i];
    __syncthreads();
    float acc = b1[t];
#pragma unroll 8
    for (int j = 0; j < LL * FF; j++) acc += sp[j] * g_W1T[j * FF + t];
    g_z[g * FF + t] = fmaxf(acc, 0.f);
}

__global__ void gs_mlp2_kernel(const float* __restrict__ W2,
                               const float* __restrict__ b2,
                               float* __restrict__ out) {
    __shared__ float sz[FF];
    int g = blockIdx.x, t = threadIdx.x;
    sz[t] = g_z[g * FF + t];
    __syncthreads();
    if (t < TT) {
        float acc = b2[t];
#pragma unroll
        for (int c = 0; c < FF; c++) acc += sz[c] * W2[t * FF + c];
        out[g * TT + t] = acc;
    }
}

extern "C" void kernel_launch(void* const* d_in, const int* in_sizes, int n_in,
                              void* d_out, int out_size) {
    const float* x     = (const float*)d_in[0];
    const void*  ei    = d_in[1];
    const void*  batch = d_in[2];
    const float* Wl    = (const float*)d_in[3];
    const float* bl    = (const float*)d_in[4];
    const float* Wr    = (const float*)d_in[5];
    const float* W1    = (const float*)d_in[6];
    const float* b1    = (const float*)d_in[7];
    const float* W2    = (const float*)d_in[8];
    const float* b2    = (const float*)d_in[9];
    float* out = (float*)d_out;

    // one-time handles (host-side only; no device memory)
    static cudaStream_t s2 = nullptr;
    static cudaEvent_t ev[16];
    if (!s2) {
        cudaStreamCreate(&s2);
        for (int i = 0; i < 16; i++)
            cudaEventCreateWithFlags(&ev[i], cudaEventDisableTiming);
    }
    cudaStream_t s0 = 0;

    size_t smem = (size_t)(FF * WPITCH * 2 + BRF * APITCH * 2) * sizeof(float);
    cudaFuncSetAttribute(gs_gemm_kernel,
                         cudaFuncAttributeMaxDynamicSharedMemorySize, (int)smem);

    // ---- preamble: CSR chain on s0; transpose+bounds forked onto s2 ----
    cudaEventRecord(ev[0], s0);                 // fork point (capture entry)
    cudaStreamWaitEvent(s2, ev[0], 0);
    gs_transpose_kernel<<<(LL * FF * FF + 255) / 256, 256, 0, s2>>>(Wl, Wr, W1);

    gs_zero_idx_kernel<<<(NN + 255) / 256, 256, 0, s0>>>();
    gs_detect_kernel<<<1, 128, 0, s0>>>((const int*)ei);
    cudaEventRecord(ev[1], s0);                 // detect done
    cudaStreamWaitEvent(s2, ev[1], 0);
    gs_bounds_kernel<<<1, GG + 1, 0, s2>>>(batch);
    cudaEventRecord(ev[2], s2);                 // transpose+bounds done

    gs_convert_count_kernel<<<(EE + 255) / 256, 256, 0, s0>>>(ei);
    gs_scan_kernel<<<1, 1024, 0, s0>>>();
    gs_fill_kernel<<<(EE + 255) / 256, 256, 0, s0>>>();
    cudaEventRecord(ev[3], s0);                 // CSR ready
    cudaStreamWaitEvent(s2, ev[3], 0);          // gathers may start
    cudaStreamWaitEvent(s0, ev[2], 0);          // gemm needs weights

    void *p_f1, *p_f2, *p_f3, *p_wlt, *p_wrt;
    cudaGetSymbolAddress(&p_f1, g_f1);
    cudaGetSymbolAddress(&p_f2, g_f2);
    cudaGetSymbolAddress(&p_f3, g_f3);
    cudaGetSymbolAddress(&p_wlt, g_WlT);
    cudaGetSymbolAddress(&p_wrt, g_WrT);
    float* fbuf_sel[3] = {(float*)p_f1, (float*)p_f2, (float*)p_f3};

    const int cbase[3] = {0, C0, C0 + C1};
    const int ccnt[3]  = {C0, C1, C2};

    const float* hin = x;
    int evi = 4;
    for (int l = 0; l < LL; l++) {
        // gather chunks on s2, each signaling its event
        for (int c = 0; c < 3; c++) {
            int blocks = (ccnt[c] * 32 + 255) / 256;
            gs_gather_kernel<<<blocks, 256, 0, s2>>>(hin, cbase[c], ccnt[c]);
            cudaEventRecord(ev[evi + c], s2);
        }
        // gemm chunks on s0, each waiting only its gather chunk
        for (int c = 0; c < 3; c++) {
            cudaStreamWaitEvent(s0, ev[evi + c], 0);
            int ctas = (ccnt[c] + BRF - 1) / BRF;
            gs_gemm_kernel<<<ctas, 512, smem, s0>>>(
                hin,
                (const float*)p_wlt + (size_t)l * FF * FF, bl + l * FF,
                (const float*)p_wrt + (size_t)l * FF * FF, fbuf_sel[l],
                cbase[c]);
        }
        evi += 3;
        if (l < LL - 1) {
            cudaEventRecord(ev[evi], s0);       // layer output complete
            cudaStreamWaitEvent(s2, ev[evi], 0);
            evi++;
        }
        hin = fbuf_sel[l];
    }

    gs_pool_kernel<<<GG, LL * FF, 0, s0>>>();
    gs_mlp1_kernel<<<GG, FF, 0, s0>>>(b1);
    gs_mlp2_kernel<<<GG, FF, 0, s0>>>(W2, b2, out);
}

// round 13
// speedup vs baseline: 1.8542x; 1.8542x over previous
#include <cuda_runtime.h>
#include <cstdint>

#define NN 50000
#define EE 800000
#define FF 128
#define LL 3
#define GG 256
#define TT 10

#define BRF 128          // rows per GEMM block
#define APITCH 36
#define WPITCH 132

// ---- scratch (device globals; no allocation allowed) ----
__device__ float g_agg[NN * FF];
__device__ float g_f1[NN * FF];
__device__ float g_f2[NN * FF];
__device__ float g_f3[NN * FF];
__device__ float g_WlT[LL * FF * FF];
__device__ float g_WrT[LL * FF * FF];
__device__ float g_W1T[LL * FF * FF];   // [384][128]
__device__ float g_pool[GG * LL * FF];
__device__ float g_z[GG * FF];
__device__ int   g_start[GG + 1];
__device__ int   g_src[EE];
__device__ int   g_dst[EE];
__device__ int   g_csr[EE];
__device__ int   g_rowptr[NN + 1];
__device__ int   g_indeg[NN];
__device__ int   g_cursor[NN];
__device__ int   g_idx64;

// ---- packed f32x2 helpers (FFMA2 — reachable only via PTX) ----
__device__ __forceinline__ unsigned long long pk2(float lo, float hi) {
    unsigned long long r;
    asm("mov.b64 %0, {%1, %2};" : "=l"(r) : "f"(lo), "f"(hi));
    return r;
}
__device__ __forceinline__ void upk2(float& lo, float& hi, unsigned long long v) {
    asm("mov.b64 {%0, %1}, %2;" : "=f"(lo), "=f"(hi) : "l"(v));
}
__device__ __forceinline__ void ffma2(unsigned long long& d,
                                      unsigned long long a, unsigned long long b) {
    asm("fma.rn.f32x2 %0, %1, %2, %0;" : "+l"(d) : "l"(a), "l"(b));
}

// ---- weight pre-transpose: Wl/Wr [l][o][k] -> [l][k][o]; W1 [c][j] -> [j][c] ----
__global__ void gs_transpose_kernel(const float* __restrict__ Wl,
                                    const float* __restrict__ Wr,
                                    const float* __restrict__ W1) {
    int idx = blockIdx.x * blockDim.x + threadIdx.x;
    if (idx < LL * FF * FF) {
        int l = idx / (FF * FF), r = idx % (FF * FF);
        int o = r / FF, k = r % FF;
        g_WlT[l * FF * FF + k * FF + o] = Wl[idx];
        g_WrT[l * FF * FF + k * FF + o] = Wr[idx];
        int c = idx / (LL * FF), j = idx % (LL * FF);
        g_W1T[j * FF + c] = W1[idx];
    }
}

__global__ void gs_zero_idx_kernel() {
    int i = blockIdx.x * blockDim.x + threadIdx.x;
    if (i < NN) g_indeg[i] = 0;
}

// ---- dtype detection (parallel): int64 edge_index has all-zero high words ----
__global__ void gs_detect_kernel(const int* __restrict__ ei32) {
    __shared__ int flag;
    if (threadIdx.x == 0) flag = 1;
    __syncthreads();
    if (ei32[2 * threadIdx.x + 1] != 0) flag = 0;
    __syncthreads();
    if (threadIdx.x == 0) g_idx64 = flag;
}

__global__ void gs_convert_count_kernel(const void* __restrict__ ei) {
    int e = blockIdx.x * blockDim.x + threadIdx.x;
    if (e >= EE) return;
    int s, d;
    if (g_idx64) {
        const long long* p = (const long long*)ei;
        s = (int)p[e]; d = (int)p[EE + e];
    } else {
        const int* p = (const int*)ei;
        s = p[e]; d = p[EE + e];
    }
    g_src[e] = s; g_dst[e] = d;
    atomicAdd(&g_indeg[d], 1);
}

__global__ void gs_scan_kernel() {
    __shared__ int ssum[1024];
    const int t = threadIdx.x;
    const int CH = (NN + 1023) / 1024;
    const int base = t * CH;
    int s = 0;
    for (int i = 0; i < CH; i++) {
        int idx = base + i;
        if (idx < NN) s += g_indeg[idx];
    }
    ssum[t] = s;
    __syncthreads();
    for (int off = 1; off < 1024; off <<= 1) {
        int v = (t >= off) ? ssum[t - off] : 0;
        __syncthreads();
        ssum[t] += v;
        __syncthreads();
    }
    int running = (t == 0) ? 0 : ssum[t - 1];
    for (int i = 0; i < CH; i++) {
        int idx = base + i;
        if (idx < NN) {
            g_rowptr[idx] = running;
            g_cursor[idx] = running;
            running += g_indeg[idx];
        }
    }
    if (t == 1023) g_rowptr[NN] = running;
}

__global__ void gs_fill_kernel() {
    int e = blockIdx.x * blockDim.x + threadIdx.x;
    if (e >= EE) return;
    int pos = atomicAdd(&g_cursor[g_dst[e]], 1);
    g_csr[pos] = g_src[e];
}

__global__ void gs_bounds_kernel(const void* __restrict__ batch) {
    int g = blockIdx.x * blockDim.x + threadIdx.x;
    if (g > GG) return;
    int is64 = g_idx64;
    const long long* b64 = (const long long*)batch;
    const int* b32 = (const int*)batch;
    int lo = 0, hi = NN;
    while (lo < hi) {
        int mid = (lo + hi) >> 1;
        long long v = is64 ? b64[mid] : (long long)b32[mid];
        if (v < (long long)g) lo = mid + 1; else hi = mid;
    }
    g_start[g] = lo;
}

// ---- gather-mean aggregation: one warp per dst node, no atomics ----
__global__ void __launch_bounds__(256) gs_gather_kernel(const float* __restrict__ h) {
    int warp = (blockIdx.x * blockDim.x + threadIdx.x) >> 5;
    int lane = threadIdx.x & 31;
    if (warp >= NN) return;
    int s0 = g_rowptr[warp], s1 = g_rowptr[warp + 1];
    float4 acc = make_float4(0.f, 0.f, 0.f, 0.f);
    int j = s0;
    for (; j + 4 <= s1; j += 4) {
        int a = g_csr[j], b = g_csr[j + 1], c = g_csr[j + 2], d = g_csr[j + 3];
        float4 v0 = reinterpret_cast<const float4*>(h + (size_t)a * FF)[lane];
        float4 v1 = reinterpret_cast<const float4*>(h + (size_t)b * FF)[lane];
        float4 v2 = reinterpret_cast<const float4*>(h + (size_t)c * FF)[lane];
        float4 v3 = reinterpret_cast<const float4*>(h + (size_t)d * FF)[lane];
        acc.x += (v0.x + v1.x) + (v2.x + v3.x);
        acc.y += (v0.y + v1.y) + (v2.y + v3.y);
        acc.z += (v0.z + v1.z) + (v2.z + v3.z);
        acc.w += (v0.w + v1.w) + (v2.w + v3.w);
    }
    for (; j < s1; j++) {
        int s = g_csr[j];
        float4 v = reinterpret_cast<const float4*>(h + (size_t)s * FF)[lane];
        acc.x += v.x; acc.y += v.y; acc.z += v.z; acc.w += v.w;
    }
    float iv = (s1 > s0) ? 1.f / (float)(s1 - s0) : 0.f;
    acc.x *= iv; acc.y *= iv; acc.z *= iv; acc.w *= iv;
    reinterpret_cast<float4*>(g_agg + (size_t)warp * FF)[lane] = acc;
}

// ---- fused SAGE layer GEMM (512 thr, 128 rows, packed f32x2 FMA) ----
__global__ void __launch_bounds__(512) gs_gemm_kernel(
    const float* __restrict__ hin,
    const float* __restrict__ WlT, const float* __restrict__ blp,
    const float* __restrict__ WrT, float* __restrict__ hout)
{
    extern __shared__ float sm[];
    float* sWl = sm;                         // 128 x WPITCH
    float* sWr = sWl + FF * WPITCH;          // 128 x WPITCH
    float* sA  = sWr + FF * WPITCH;          // BRF x APITCH
    float* sH  = sA + BRF * APITCH;          // BRF x APITCH
    const int t = threadIdx.x;
    const int row0 = blockIdx.x * BRF;

    for (int i = t; i < FF * FF / 4; i += 512) {
        int k = i >> 5, c4 = i & 31;
        float4 wl = reinterpret_cast<const float4*>(WlT)[i];
        float4 wr = reinterpret_cast<const float4*>(WrT)[i];
        reinterpret_cast<float4*>(sWl + k * WPITCH)[c4] = wl;
        reinterpret_cast<float4*>(sWr + k * WPITCH)[c4] = wr;
    }

    const int tc = t & 15, tr = t >> 4;      // 16 col-groups x 32 row-groups
    const int cA = tc * 4, cB = 64 + tc * 4, r0 = tr * 4;

    // packed accumulators: 4 rows x 4 col-pairs (cols cA,cA+1 | cA+2,cA+3 | cB.. )
    unsigned long long acc2[4][4];
#pragma unroll
    for (int i = 0; i < 4; i++)
#pragma unroll
        for (int j = 0; j < 4; j++) acc2[i][j] = 0ull;

    for (int kc = 0; kc < FF; kc += 32) {
        __syncthreads();
        for (int i = t; i < BRF * 8; i += 512) {
            int r = i >> 3, k4 = i & 7;
            int gr = row0 + r; if (gr >= NN) gr = NN - 1;
            reinterpret_cast<float4*>(sA + r * APITCH)[k4] =
                reinterpret_cast<const float4*>(g_agg + (size_t)gr * FF + kc)[k4];
            reinterpret_cast<float4*>(sH + r * APITCH)[k4] =
                reinterpret_cast<const float4*>(hin + (size_t)gr * FF + kc)[k4];
        }
        __syncthreads();
#pragma unroll
        for (int k = 0; k < 32; k++) {
            const float* wrow_l = sWl + (kc + k) * WPITCH;
            const float* wrow_r = sWr + (kc + k) * WPITCH;
            float4 wl0 = *reinterpret_cast<const float4*>(wrow_l + cA);
            float4 wl1 = *reinterpret_cast<const float4*>(wrow_l + cB);
            float4 wr0 = *reinterpret_cast<const float4*>(wrow_r + cA);
            float4 wr1 = *reinterpret_cast<const float4*>(wrow_r + cB);
            unsigned long long wl00 = pk2(wl0.x, wl0.y), wl01 = pk2(wl0.z, wl0.w);
            unsigned long long wl10 = pk2(wl1.x, wl1.y), wl11 = pk2(wl1.z, wl1.w);
            unsigned long long wr00 = pk2(wr0.x, wr0.y), wr01 = pk2(wr0.z, wr0.w);
            unsigned long long wr10 = pk2(wr1.x, wr1.y), wr11 = pk2(wr1.z, wr1.w);
#pragma unroll
            for (int i = 0; i < 4; i++) {
                float a = sA[(r0 + i) * APITCH + k];
                float h = sH[(r0 + i) * APITCH + k];
                unsigned long long aa = pk2(a, a);
                unsigned long long hh = pk2(h, h);
                ffma2(acc2[i][0], aa, wl00); ffma2(acc2[i][0], hh, wr00);
                ffma2(acc2[i][1], aa, wl01); ffma2(acc2[i][1], hh, wr01);
                ffma2(acc2[i][2], aa, wl10); ffma2(acc2[i][2], hh, wr10);
                ffma2(acc2[i][3], aa, wl11); ffma2(acc2[i][3], hh, wr11);
            }
        }
    }

    float4 b0 = *reinterpret_cast<const float4*>(blp + cA);
    float4 b1v = *reinterpret_cast<const float4*>(blp + cB);
#pragma unroll
    for (int i = 0; i < 4; i++) {
        int gr = row0 + r0 + i;
        if (gr < NN) {
            float4 o0, o1;
            upk2(o0.x, o0.y, acc2[i][0]);
            upk2(o0.z, o0.w, acc2[i][1]);
            upk2(o1.x, o1.y, acc2[i][2]);
            upk2(o1.z, o1.w, acc2[i][3]);
            o0.x += b0.x; o0.y += b0.y; o0.z += b0.z; o0.w += b0.w;
            o1.x += b1v.x; o1.y += b1v.y; o1.z += b1v.z; o1.w += b1v.w;
            *reinterpret_cast<float4*>(hout + (size_t)gr * FF + cA) = o0;
            *reinterpret_cast<float4*>(hout + (size_t)gr * FF + cB) = o1;
        }
    }
}

// ---- global max pool over each graph segment; one block per graph ----
__global__ void gs_pool_kernel() {
    int g = blockIdx.x;
    int s = g_start[g], e = g_start[g + 1];
    int t = threadIdx.x;            // 0..383
    int l = t >> 7, c = t & 127;
    const float* f = (l == 0) ? g_f1 : (l == 1) ? g_f2 : g_f3;
    float m = -3.402823466e38f;
    int i = s;
    for (; i + 4 <= e; i += 4) {
        float v0 = f[(size_t)(i + 0) * FF + c];
        float v1 = f[(size_t)(i + 1) * FF + c];
        float v2 = f[(size_t)(i + 2) * FF + c];
        float v3 = f[(size_t)(i + 3) * FF + c];
        m = fmaxf(m, fmaxf(fmaxf(v0, v1), fmaxf(v2, v3)));
    }
    for (; i < e; i++) m = fmaxf(m, f[(size_t)i * FF + c]);
    g_pool[g * (LL * FF) + t] = m;
}

// ---- MLP layer 1: z = relu(pool @ W1^T + b1) ----
__global__ void gs_mlp1_kernel(const float* __restrict__ b1) {
    __shared__ float sp[LL * FF];
    int g = blockIdx.x, t = threadIdx.x;   // 128 threads
    for (int i = t; i < LL * FF; i += FF) sp[i] = g_pool[g * (LL * FF) + i];
    __syncthreads();
    float acc = b1[t];
#pragma unroll 8
    for (int j = 0; j < LL * FF; j++) acc += sp[j] * g_W1T[j * FF + t];
    g_z[g * FF + t] = fmaxf(acc, 0.f);
}

// ---- MLP layer 2: out = z @ W2^T + b2 ----
__global__ void gs_mlp2_kernel(const float* __restrict__ W2,
                               const float* __restrict__ b2,
                               float* __restrict__ out) {
    __shared__ float sz[FF];
    int g = blockIdx.x, t = threadIdx.x;   // 128 threads
    sz[t] = g_z[g * FF + t];
    __syncthreads();
    if (t < TT) {
        float acc = b2[t];
#pragma unroll
        for (int c = 0; c < FF; c++) acc += sz[c] * W2[t * FF + c];
        out[g * TT + t] = acc;
    }
}

extern "C" void kernel_launch(void* const* d_in, const int* in_sizes, int n_in,
                              void* d_out, int out_size) {
    const float* x     = (const float*)d_in[0];
    const void*  ei    = d_in[1];
    const void*  batch = d_in[2];
    const float* Wl    = (const float*)d_in[3];
    const float* bl    = (const float*)d_in[4];
    const float* Wr    = (const float*)d_in[5];
    const float* W1    = (const float*)d_in[6];
    const float* b1    = (const float*)d_in[7];
    const float* W2    = (const float*)d_in[8];
    const float* b2    = (const float*)d_in[9];
    float* out = (float*)d_out;

    size_t smem = (size_t)(FF * WPITCH * 2 + BRF * APITCH * 2) * sizeof(float);
    cudaFuncSetAttribute(gs_gemm_kernel,
                         cudaFuncAttributeMaxDynamicSharedMemorySize, (int)smem);

    gs_transpose_kernel<<<(LL * FF * FF + 255) / 256, 256>>>(Wl, Wr, W1);
    gs_zero_idx_kernel<<<(NN + 255) / 256, 256>>>();
    gs_detect_kernel<<<1, 128>>>((const int*)ei);
    gs_convert_count_kernel<<<(EE + 255) / 256, 256>>>(ei);
    gs_scan_kernel<<<1, 1024>>>();
    gs_fill_kernel<<<(EE + 255) / 256, 256>>>();
    gs_bounds_kernel<<<1, GG + 1>>>(batch);

    void *p_f1, *p_f2, *p_f3, *p_wlt, *p_wrt;
    cudaGetSymbolAddress(&p_f1, g_f1);
    cudaGetSymbolAddress(&p_f2, g_f2);
    cudaGetSymbolAddress(&p_f3, g_f3);
    cudaGetSymbolAddress(&p_wlt, g_WlT);
    cudaGetSymbolAddress(&p_wrt, g_WrT);
    float* fbuf_sel[3] = {(float*)p_f1, (float*)p_f2, (float*)p_f3};

    const float* hin = x;
    for (int l = 0; l < LL; l++) {
        gs_gather_kernel<<<(NN * 32 + 255) / 256, 256>>>(hin);
        gs_gemm_kernel<<<(NN + BRF - 1) / BRF, 512, smem>>>(
            hin,
            (const float*)p_wlt + (size_t)l * FF * FF, bl + l * FF,
            (const float*)p_wrt + (size_t)l * FF * FF, fbuf_sel[l]);
        hin = fbuf_sel[l];
    }

    gs_pool_kernel<<<GG, LL * FF>>>();
    gs_mlp1_kernel<<<GG, FF>>>(b1);
    gs_mlp2_kernel<<<GG, FF>>>(W2, b2, out);
}

// round 14
// speedup vs baseline: 1.9508x; 1.0521x over previous
#include <cuda_runtime.h>
#include <cstdint>

#define NN 50000
#define EE 800000
#define FF 128
#define LL 3
#define GG 256
#define TT 10

#define BRF 128          // rows per GEMM block
#define APITCH 36
#define WPITCH 132

// ---- scratch (device globals; no allocation allowed) ----
__device__ float g_agg[NN * FF];
__device__ float g_f1[NN * FF];
__device__ float g_f2[NN * FF];
__device__ float g_f3[NN * FF];
__device__ float g_WlT[LL * FF * FF];
__device__ float g_WrT[LL * FF * FF];
__device__ float g_W1T[LL * FF * FF];   // [384][128]
__device__ float g_pool[GG * LL * FF];
__device__ float g_z[GG * FF];
__device__ int   g_start[GG + 1];
__device__ int   g_src[EE];
__device__ int   g_dst[EE];
__device__ int   g_csr[EE];
__device__ int   g_rowptr[NN + 1];
__device__ int   g_indeg[NN];
__device__ int   g_cursor[NN];
__device__ int   g_idx64;

// ---- packed f32x2 helpers (FFMA2 — reachable only via PTX) ----
__device__ __forceinline__ unsigned long long pk2(float lo, float hi) {
    unsigned long long r;
    asm("mov.b64 %0, {%1, %2};" : "=l"(r) : "f"(lo), "f"(hi));
    return r;
}
__device__ __forceinline__ void upk2(float& lo, float& hi, unsigned long long v) {
    asm("mov.b64 {%0, %1}, %2;" : "=f"(lo), "=f"(hi) : "l"(v));
}
__device__ __forceinline__ void ffma2(unsigned long long& d,
                                      unsigned long long a, unsigned long long b) {
    asm("fma.rn.f32x2 %0, %1, %2, %0;" : "+l"(d) : "l"(a), "l"(b));
}

// ---- fused init: zero indeg + weight pre-transpose ----
__global__ void gs_init_kernel(const float* __restrict__ Wl,
                               const float* __restrict__ Wr,
                               const float* __restrict__ W1) {
    int idx = blockIdx.x * blockDim.x + threadIdx.x;
    if (idx < NN) g_indeg[idx] = 0;
    if (idx < LL * FF * FF) {
        int l = idx / (FF * FF), r = idx % (FF * FF);
        int o = r / FF, k = r % FF;
        g_WlT[l * FF * FF + k * FF + o] = Wl[idx];
        g_WrT[l * FF * FF + k * FF + o] = Wr[idx];
        int c = idx / (LL * FF), j = idx % (LL * FF);
        g_W1T[j * FF + c] = W1[idx];
    }
}

// ---- dtype detection (parallel): int64 edge_index has all-zero high words ----
__global__ void gs_detect_kernel(const int* __restrict__ ei32) {
    __shared__ int flag;
    if (threadIdx.x == 0) flag = 1;
    __syncthreads();
    if (ei32[2 * threadIdx.x + 1] != 0) flag = 0;
    __syncthreads();
    if (threadIdx.x == 0) g_idx64 = flag;
}

__global__ void gs_convert_count_kernel(const void* __restrict__ ei) {
    int e = blockIdx.x * blockDim.x + threadIdx.x;
    if (e >= EE) return;
    int s, d;
    if (g_idx64) {
        const long long* p = (const long long*)ei;
        s = (int)p[e]; d = (int)p[EE + e];
    } else {
        const int* p = (const int*)ei;
        s = p[e]; d = p[EE + e];
    }
    g_src[e] = s; g_dst[e] = d;
    atomicAdd(&g_indeg[d], 1);
}

__global__ void gs_scan_kernel() {
    __shared__ int ssum[1024];
    const int t = threadIdx.x;
    const int CH = (NN + 1023) / 1024;
    const int base = t * CH;
    int s = 0;
    for (int i = 0; i < CH; i++) {
        int idx = base + i;
        if (idx < NN) s += g_indeg[idx];
    }
    ssum[t] = s;
    __syncthreads();
    for (int off = 1; off < 1024; off <<= 1) {
        int v = (t >= off) ? ssum[t - off] : 0;
        __syncthreads();
        ssum[t] += v;
        __syncthreads();
    }
    int running = (t == 0) ? 0 : ssum[t - 1];
    for (int i = 0; i < CH; i++) {
        int idx = base + i;
        if (idx < NN) {
            g_rowptr[idx] = running;
            g_cursor[idx] = running;
            running += g_indeg[idx];
        }
    }
    if (t == 1023) g_rowptr[NN] = running;
}

__global__ void gs_fill_kernel() {
    int e = blockIdx.x * blockDim.x + threadIdx.x;
    if (e >= EE) return;
    int pos = atomicAdd(&g_cursor[g_dst[e]], 1);
    g_csr[pos] = g_src[e];
}

// ---- segment bounds (parallel blocks) ----
__global__ void gs_bounds_kernel(const void* __restrict__ batch) {
    int g = blockIdx.x * blockDim.x + threadIdx.x;
    if (g > GG) return;
    int is64 = g_idx64;
    const long long* b64 = (const long long*)batch;
    const int* b32 = (const int*)batch;
    int lo = 0, hi = NN;
    while (lo < hi) {
        int mid = (lo + hi) >> 1;
        long long v = is64 ? b64[mid] : (long long)b32[mid];
        if (v < (long long)g) lo = mid + 1; else hi = mid;
    }
    g_start[g] = lo;
}

// ---- gather-mean aggregation: one warp per dst node, no atomics ----
__global__ void __launch_bounds__(256) gs_gather_kernel(const float* __restrict__ h) {
    int warp = (blockIdx.x * blockDim.x + threadIdx.x) >> 5;
    int lane = threadIdx.x & 31;
    if (warp >= NN) return;
    int s0 = g_rowptr[warp], s1 = g_rowptr[warp + 1];
    float4 acc = make_float4(0.f, 0.f, 0.f, 0.f);
    int j = s0;
    for (; j + 4 <= s1; j += 4) {
        int a = g_csr[j], b = g_csr[j + 1], c = g_csr[j + 2], d = g_csr[j + 3];
        float4 v0 = reinterpret_cast<const float4*>(h + (size_t)a * FF)[lane];
        float4 v1 = reinterpret_cast<const float4*>(h + (size_t)b * FF)[lane];
        float4 v2 = reinterpret_cast<const float4*>(h + (size_t)c * FF)[lane];
        float4 v3 = reinterpret_cast<const float4*>(h + (size_t)d * FF)[lane];
        acc.x += (v0.x + v1.x) + (v2.x + v3.x);
        acc.y += (v0.y + v1.y) + (v2.y + v3.y);
        acc.z += (v0.z + v1.z) + (v2.z + v3.z);
        acc.w += (v0.w + v1.w) + (v2.w + v3.w);
    }
    for (; j < s1; j++) {
        int s = g_csr[j];
        float4 v = reinterpret_cast<const float4*>(h + (size_t)s * FF)[lane];
        acc.x += v.x; acc.y += v.y; acc.z += v.z; acc.w += v.w;
    }
    float iv = (s1 > s0) ? 1.f / (float)(s1 - s0) : 0.f;
    acc.x *= iv; acc.y *= iv; acc.z *= iv; acc.w *= iv;
    reinterpret_cast<float4*>(g_agg + (size_t)warp * FF)[lane] = acc;
}

// ---- fused SAGE layer GEMM: FFMA2 + register-prefetch double buffering ----
__global__ void __launch_bounds__(512) gs_gemm_kernel(
    const float* __restrict__ hin,
    const float* __restrict__ WlT, const float* __restrict__ blp,
    const float* __restrict__ WrT, float* __restrict__ hout)
{
    extern __shared__ float sm[];
    float* sWl = sm;                         // 128 x WPITCH
    float* sWr = sWl + FF * WPITCH;          // 128 x WPITCH
    float* sA  = sWr + FF * WPITCH;          // BRF x APITCH
    float* sH  = sA + BRF * APITCH;          // BRF x APITCH
    const int t = threadIdx.x;
    const int row0 = blockIdx.x * BRF;

    for (int i = t; i < FF * FF / 4; i += 512) {
        int k = i >> 5, c4 = i & 31;
        float4 wl = reinterpret_cast<const float4*>(WlT)[i];
        float4 wr = reinterpret_cast<const float4*>(WrT)[i];
        reinterpret_cast<float4*>(sWl + k * WPITCH)[c4] = wl;
        reinterpret_cast<float4*>(sWr + k * WPITCH)[c4] = wr;
    }

    // per-thread stage indices (2 float4 per matrix per chunk)
    const int i0 = t, i1 = t + 512;
    const int r0s = i0 >> 3, k40 = i0 & 7;
    const int r1s = i1 >> 3, k41 = i1 & 7;
    int gr0 = row0 + r0s; if (gr0 >= NN) gr0 = NN - 1;
    int gr1 = row0 + r1s; if (gr1 >= NN) gr1 = NN - 1;

    const int tc = t & 15, tr = t >> 4;
    const int cA = tc * 4, cB = 64 + tc * 4, r0 = tr * 4;

    unsigned long long acc2[4][4];
#pragma unroll
    for (int i = 0; i < 4; i++)
#pragma unroll
        for (int j = 0; j < 4; j++) acc2[i][j] = 0ull;

    // prefetch chunk 0
    float4 rA0 = reinterpret_cast<const float4*>(g_agg + (size_t)gr0 * FF)[k40];
    float4 rA1 = reinterpret_cast<const float4*>(g_agg + (size_t)gr1 * FF)[k41];
    float4 rH0 = reinterpret_cast<const float4*>(hin + (size_t)gr0 * FF)[k40];
    float4 rH1 = reinterpret_cast<const float4*>(hin + (size_t)gr1 * FF)[k41];

#pragma unroll
    for (int ck = 0; ck < 4; ck++) {
        const int kc = ck * 32;
        __syncthreads();   // previous compute done (WAR)
        reinterpret_cast<float4*>(sA + r0s * APITCH)[k40] = rA0;
        reinterpret_cast<float4*>(sA + r1s * APITCH)[k41] = rA1;
        reinterpret_cast<float4*>(sH + r0s * APITCH)[k40] = rH0;
        reinterpret_cast<float4*>(sH + r1s * APITCH)[k41] = rH1;
        __syncthreads();
        if (ck < 3) {   // prefetch next chunk; overlaps with compute below
            const int kn = kc + 32;
            rA0 = reinterpret_cast<const float4*>(g_agg + (size_t)gr0 * FF + kn)[k40];
            rA1 = reinterpret_cast<const float4*>(g_agg + (size_t)gr1 * FF + kn)[k41];
            rH0 = reinterpret_cast<const float4*>(hin + (size_t)gr0 * FF + kn)[k40];
            rH1 = reinterpret_cast<const float4*>(hin + (size_t)gr1 * FF + kn)[k41];
        }
#pragma unroll
        for (int k = 0; k < 32; k++) {
            const float* wrow_l = sWl + (kc + k) * WPITCH;
            const float* wrow_r = sWr + (kc + k) * WPITCH;
            // weights read pre-packed as f32x2 pairs (16B-aligned)
            longlong2 wlA = *reinterpret_cast<const longlong2*>(wrow_l + cA);
            longlong2 wlB = *reinterpret_cast<const longlong2*>(wrow_l + cB);
            longlong2 wrA = *reinterpret_cast<const longlong2*>(wrow_r + cA);
            longlong2 wrB = *reinterpret_cast<const longlong2*>(wrow_r + cB);
#pragma unroll
            for (int i = 0; i < 4; i++) {
                float a = sA[(r0 + i) * APITCH + k];
                float h = sH[(r0 + i) * APITCH + k];
                unsigned long long aa = pk2(a, a);
                unsigned long long hh = pk2(h, h);
                ffma2(acc2[i][0], aa, (unsigned long long)wlA.x);
                ffma2(acc2[i][0], hh, (unsigned long long)wrA.x);
                ffma2(acc2[i][1], aa, (unsigned long long)wlA.y);
                ffma2(acc2[i][1], hh, (unsigned long long)wrA.y);
                ffma2(acc2[i][2], aa, (unsigned long long)wlB.x);
                ffma2(acc2[i][2], hh, (unsigned long long)wrB.x);
                ffma2(acc2[i][3], aa, (unsigned long long)wlB.y);
                ffma2(acc2[i][3], hh, (unsigned long long)wrB.y);
            }
        }
    }

    float4 b0 = *reinterpret_cast<const float4*>(blp + cA);
    float4 b1v = *reinterpret_cast<const float4*>(blp + cB);
#pragma unroll
    for (int i = 0; i < 4; i++) {
        int gr = row0 + r0 + i;
        if (gr < NN) {
            float4 o0, o1;
            upk2(o0.x, o0.y, acc2[i][0]);
            upk2(o0.z, o0.w, acc2[i][1]);
            upk2(o1.x, o1.y, acc2[i][2]);
            upk2(o1.z, o1.w, acc2[i][3]);
            o0.x += b0.x; o0.y += b0.y; o0.z += b0.z; o0.w += b0.w;
            o1.x += b1v.x; o1.y += b1v.y; o1.z += b1v.z; o1.w += b1v.w;
            *reinterpret_cast<float4*>(hout + (size_t)gr * FF + cA) = o0;
            *reinterpret_cast<float4*>(hout + (size_t)gr * FF + cB) = o1;
        }
    }
}

// ---- global max pool over each graph segment; one block per graph ----
__global__ void gs_pool_kernel() {
    int g = blockIdx.x;
    int s = g_start[g], e = g_start[g + 1];
    int t = threadIdx.x;            // 0..383
    int l = t >> 7, c = t & 127;
    const float* f = (l == 0) ? g_f1 : (l == 1) ? g_f2 : g_f3;
    float m = -3.402823466e38f;
    int i = s;
    for (; i + 4 <= e; i += 4) {
        float v0 = f[(size_t)(i + 0) * FF + c];
        float v1 = f[(size_t)(i + 1) * FF + c];
        float v2 = f[(size_t)(i + 2) * FF + c];
        float v3 = f[(size_t)(i + 3) * FF + c];
        m = fmaxf(m, fmaxf(fmaxf(v0, v1), fmaxf(v2, v3)));
    }
    for (; i < e; i++) m = fmaxf(m, f[(size_t)i * FF + c]);
    g_pool[g * (LL * FF) + t] = m;
}

// ---- MLP layer 1: z = relu(pool @ W1^T + b1) ----
__global__ void gs_mlp1_kernel(const float* __restrict__ b1) {
    __shared__ float sp[LL * FF];
    int g = blockIdx.x, t = threadIdx.x;   // 128 threads
    for (int i = t; i < LL * FF; i += FF) sp[i] = g_pool[g * (LL * FF) + i];
    __syncthreads();
    float acc = b1[t];
#pragma unroll 8
    for (int j = 0; j < LL * FF; j++) acc += sp[j] * g_W1T[j * FF + t];
    g_z[g * FF + t] = fmaxf(acc, 0.f);
}

// ---- MLP layer 2: out = z @ W2^T + b2 ----
__global__ void gs_mlp2_kernel(const float* __restrict__ W2,
                               const float* __restrict__ b2,
                               float* __restrict__ out) {
    __shared__ float sz[FF];
    int g = blockIdx.x, t = threadIdx.x;   // 128 threads
    sz[t] = g_z[g * FF + t];
    __syncthreads();
    if (t < TT) {
        float acc = b2[t];
#pragma unroll
        for (int c = 0; c < FF; c++) acc += sz[c] * W2[t * FF + c];
        out[g * TT + t] = acc;
    }
}

extern "C" void kernel_launch(void* const* d_in, const int* in_sizes, int n_in,
                              void* d_out, int out_size) {
    const float* x     = (const float*)d_in[0];
    const void*  ei    = d_in[1];
    const void*  batch = d_in[2];
    const float* Wl    = (const float*)d_in[3];
    const float* bl    = (const float*)d_in[4];
    const float* Wr    = (const float*)d_in[5];
    const float* W1    = (const float*)d_in[6];
    const float* b1    = (const float*)d_in[7];
    const float* W2    = (const float*)d_in[8];
    const float* b2    = (const float*)d_in[9];
    float* out = (float*)d_out;

    size_t smem = (size_t)(FF * WPITCH * 2 + BRF * APITCH * 2) * sizeof(float);
    cudaFuncSetAttribute(gs_gemm_kernel,
                         cudaFuncAttributeMaxDynamicSharedMemorySize, (int)smem);

    gs_init_kernel<<<(NN + 255) / 256, 256>>>(Wl, Wr, W1);
    gs_detect_kernel<<<1, 128>>>((const int*)ei);
    gs_convert_count_kernel<<<(EE + 255) / 256, 256>>>(ei);
    gs_scan_kernel<<<1, 1024>>>();
    gs_fill_kernel<<<(EE + 255) / 256, 256>>>();
    gs_bounds_kernel<<<(GG + 32) / 32, 32>>>(batch);

    void *p_f1, *p_f2, *p_f3, *p_wlt, *p_wrt;
    cudaGetSymbolAddress(&p_f1, g_f1);
    cudaGetSymbolAddress(&p_f2, g_f2);
    cudaGetSymbolAddress(&p_f3, g_f3);
    cudaGetSymbolAddress(&p_wlt, g_WlT);
    cudaGetSymbolAddress(&p_wrt, g_WrT);
    float* fbuf_sel[3] = {(float*)p_f1, (float*)p_f2, (float*)p_f3};

    const float* hin = x;
    for (int l = 0; l < LL; l++) {
        gs_gather_kernel<<<(NN * 32 + 255) / 256, 256>>>(hin);
        gs_gemm_kernel<<<(NN + BRF - 1) / BRF, 512, smem>>>(
            hin,
            (const float*)p_wlt + (size_t)l * FF * FF, bl + l * FF,
            (const float*)p_wrt + (size_t)l * FF * FF, fbuf_sel[l]);
        hin = fbuf_sel[l];
    }

    gs_pool_kernel<<<GG, LL * FF>>>();
    gs_mlp1_kernel<<<GG, FF>>>(b1);
    gs_mlp2_kernel<<<GG, FF>>>(W2, b2, out);
}

// round 15
// speedup vs baseline: 2.2864x; 1.1720x over previous
#include <cuda_runtime.h>
#include <cstdint>

#define NN 50000
#define EE 800000
#define FF 128
#define LL 3
#define GG 256
#define TT 10

#define BRF 128          // rows per GEMM block
#define APITCH 36
#define WPITCH 132

#define SB 64            // scan blocks
#define SCH ((NN + SB * 256 - 1) / (SB * 256))   // elems per thread = 4
#define SBLK (SCH * 256)                          // elems per block = 1024

// ---- scratch (device globals; no allocation allowed) ----
__device__ float g_agg[NN * FF];
__device__ float g_f1[NN * FF];
__device__ float g_f2[NN * FF];
__device__ float g_f3[NN * FF];
__device__ float g_WlT[LL * FF * FF];
__device__ float g_WrT[LL * FF * FF];
__device__ float g_W1T[LL * FF * FF];   // [384][128]
__device__ float g_pool[GG * LL * FF];
__device__ float g_z[GG * FF];
__device__ int   g_start[GG + 1];
__device__ int   g_src[EE];
__device__ int   g_dst[EE];
__device__ int   g_csr[EE];
__device__ int   g_rowptr[NN + 1];
__device__ int   g_indeg[NN];
__device__ int   g_cursor[NN];
__device__ int   g_bsum[SB + 1];
__device__ int   g_idx64;

// ---- packed f32x2 helpers (FFMA2 — reachable only via PTX) ----
__device__ __forceinline__ unsigned long long pk2(float lo, float hi) {
    unsigned long long r;
    asm("mov.b64 %0, {%1, %2};" : "=l"(r) : "f"(lo), "f"(hi));
    return r;
}
__device__ __forceinline__ void upk2(float& lo, float& hi, unsigned long long v) {
    asm("mov.b64 {%0, %1}, %2;" : "=f"(lo), "=f"(hi) : "l"(v));
}
__device__ __forceinline__ void ffma2(unsigned long long& d,
                                      unsigned long long a, unsigned long long b) {
    asm("fma.rn.f32x2 %0, %1, %2, %0;" : "+l"(d) : "l"(a), "l"(b));
}

// ---- fused init: zero indeg + weight pre-transpose ----
__global__ void gs_init_kernel(const float* __restrict__ Wl,
                               const float* __restrict__ Wr,
                               const float* __restrict__ W1) {
    int idx = blockIdx.x * blockDim.x + threadIdx.x;
    if (idx < NN) g_indeg[idx] = 0;
    if (idx < LL * FF * FF) {
        int l = idx / (FF * FF), r = idx % (FF * FF);
        int o = r / FF, k = r % FF;
        g_WlT[l * FF * FF + k * FF + o] = Wl[idx];
        g_WrT[l * FF * FF + k * FF + o] = Wr[idx];
        int c = idx / (LL * FF), j = idx % (LL * FF);
        g_W1T[j * FF + c] = W1[idx];
    }
}

// ---- dtype detection (parallel): int64 edge_index has all-zero high words ----
__global__ void gs_detect_kernel(const int* __restrict__ ei32) {
    __shared__ int flag;
    if (threadIdx.x == 0) flag = 1;
    __syncthreads();
    if (ei32[2 * threadIdx.x + 1] != 0) flag = 0;
    __syncthreads();
    if (threadIdx.x == 0) g_idx64 = flag;
}

__global__ void gs_convert_count_kernel(const void* __restrict__ ei) {
    int e = blockIdx.x * blockDim.x + threadIdx.x;
    if (e >= EE) return;
    int s, d;
    if (g_idx64) {
        const long long* p = (const long long*)ei;
        s = (int)p[e]; d = (int)p[EE + e];
    } else {
        const int* p = (const int*)ei;
        s = p[e]; d = p[EE + e];
    }
    g_src[e] = s; g_dst[e] = d;
    atomicAdd(&g_indeg[d], 1);
}

// ---- multi-block scan phase 1: per-block chunk sums ----
__global__ void gs_scan1_kernel() {
    __shared__ int ssum[256];
    const int t = threadIdx.x, b = blockIdx.x;
    int s = 0;
    int base = b * SBLK + t;
#pragma unroll
    for (int i = 0; i < SCH; i++) {
        int idx = base + i * 256;
        if (idx < NN) s += g_indeg[idx];
    }
    ssum[t] = s;
    __syncthreads();
    for (int off = 128; off > 0; off >>= 1) {
        if (t < off) ssum[t] += ssum[t + off];
        __syncthreads();
    }
    if (t == 0) g_bsum[b] = ssum[0];
}

// ---- multi-block scan phase 2: exclusive scan of SB block sums (tiny) ----
__global__ void gs_scan2_kernel() {
    __shared__ int sv[SB];
    const int t = threadIdx.x;   // SB threads
    sv[t] = g_bsum[t];
    __syncthreads();
    // Hillis-Steele inclusive
    for (int off = 1; off < SB; off <<= 1) {
        int v = (t >= off) ? sv[t - off] : 0;
        __syncthreads();
        sv[t] += v;
        __syncthreads();
    }
    g_bsum[t] = (t == 0) ? 0 : sv[t - 1];   // exclusive
    if (t == SB - 1) g_rowptr[NN] = sv[SB - 1];
}

// ---- multi-block scan phase 3: per-block prefix + write rowptr/cursor ----
__global__ void gs_scan3_kernel() {
    __shared__ int ssum[256];
    const int t = threadIdx.x, b = blockIdx.x;
    int vals[SCH];
    int s = 0;
    const int base = b * SBLK + t * SCH;   // contiguous per-thread run
#pragma unroll
    for (int i = 0; i < SCH; i++) {
        int idx = base + i;
        vals[i] = (idx < NN) ? g_indeg[idx] : 0;
        s += vals[i];
    }
    ssum[t] = s;
    __syncthreads();
    for (int off = 1; off < 256; off <<= 1) {
        int v = (t >= off) ? ssum[t - off] : 0;
        __syncthreads();
        ssum[t] += v;
        __syncthreads();
    }
    int running = g_bsum[b] + ((t == 0) ? 0 : ssum[t - 1]);
#pragma unroll
    for (int i = 0; i < SCH; i++) {
        int idx = base + i;
        if (idx < NN) {
            g_rowptr[idx] = running;
            g_cursor[idx] = running;
            running += vals[i];
        }
    }
}

__global__ void gs_fill_kernel() {
    int e = blockIdx.x * blockDim.x + threadIdx.x;
    if (e >= EE) return;
    int pos = atomicAdd(&g_cursor[g_dst[e]], 1);
    g_csr[pos] = g_src[e];
}

// ---- segment bounds (parallel blocks) ----
__global__ void gs_bounds_kernel(const void* __restrict__ batch) {
    int g = blockIdx.x * blockDim.x + threadIdx.x;
    if (g > GG) return;
    int is64 = g_idx64;
    const long long* b64 = (const long long*)batch;
    const int* b32 = (const int*)batch;
    int lo = 0, hi = NN;
    while (lo < hi) {
        int mid = (lo + hi) >> 1;
        long long v = is64 ? b64[mid] : (long long)b32[mid];
        if (v < (long long)g) lo = mid + 1; else hi = mid;
    }
    g_start[g] = lo;
}

// ---- gather-mean aggregation: one warp per dst node, no atomics ----
__global__ void __launch_bounds__(256) gs_gather_kernel(const float* __restrict__ h) {
    int warp = (blockIdx.x * blockDim.x + threadIdx.x) >> 5;
    int lane = threadIdx.x & 31;
    if (warp >= NN) return;
    int s0 = g_rowptr[warp], s1 = g_rowptr[warp + 1];
    float4 acc = make_float4(0.f, 0.f, 0.f, 0.f);
    int j = s0;
    for (; j + 4 <= s1; j += 4) {
        int a = g_csr[j], b = g_csr[j + 1], c = g_csr[j + 2], d = g_csr[j + 3];
        float4 v0 = reinterpret_cast<const float4*>(h + (size_t)a * FF)[lane];
        float4 v1 = reinterpret_cast<const float4*>(h + (size_t)b * FF)[lane];
        float4 v2 = reinterpret_cast<const float4*>(h + (size_t)c * FF)[lane];
        float4 v3 = reinterpret_cast<const float4*>(h + (size_t)d * FF)[lane];
        acc.x += (v0.x + v1.x) + (v2.x + v3.x);
        acc.y += (v0.y + v1.y) + (v2.y + v3.y);
        acc.z += (v0.z + v1.z) + (v2.z + v3.z);
        acc.w += (v0.w + v1.w) + (v2.w + v3.w);
    }
    for (; j < s1; j++) {
        int s = g_csr[j];
        float4 v = reinterpret_cast<const float4*>(h + (size_t)s * FF)[lane];
        acc.x += v.x; acc.y += v.y; acc.z += v.z; acc.w += v.w;
    }
    float iv = (s1 > s0) ? 1.f / (float)(s1 - s0) : 0.f;
    acc.x *= iv; acc.y *= iv; acc.z *= iv; acc.w *= iv;
    reinterpret_cast<float4*>(g_agg + (size_t)warp * FF)[lane] = acc;
}

// ---- fused SAGE layer GEMM: FFMA2 + register-prefetch double buffering ----
__global__ void __launch_bounds__(512) gs_gemm_kernel(
    const float* __restrict__ hin,
    const float* __restrict__ WlT, const float* __restrict__ blp,
    const float* __restrict__ WrT, float* __restrict__ hout)
{
    extern __shared__ float sm[];
    float* sWl = sm;                         // 128 x WPITCH
    float* sWr = sWl + FF * WPITCH;          // 128 x WPITCH
    float* sA  = sWr + FF * WPITCH;          // BRF x APITCH
    float* sH  = sA + BRF * APITCH;          // BRF x APITCH
    const int t = threadIdx.x;
    const int row0 = blockIdx.x * BRF;

    for (int i = t; i < FF * FF / 4; i += 512) {
        int k = i >> 5, c4 = i & 31;
        float4 wl = reinterpret_cast<const float4*>(WlT)[i];
        float4 wr = reinterpret_cast<const float4*>(WrT)[i];
        reinterpret_cast<float4*>(sWl + k * WPITCH)[c4] = wl;
        reinterpret_cast<float4*>(sWr + k * WPITCH)[c4] = wr;
    }

    const int i0 = t, i1 = t + 512;
    const int r0s = i0 >> 3, k40 = i0 & 7;
    const int r1s = i1 >> 3, k41 = i1 & 7;
    int gr0 = row0 + r0s; if (gr0 >= NN) gr0 = NN - 1;
    int gr1 = row0 + r1s; if (gr1 >= NN) gr1 = NN - 1;

    const int tc = t & 15, tr = t >> 4;
    const int cA = tc * 4, cB = 64 + tc * 4, r0 = tr * 4;

    unsigned long long acc2[4][4];
#pragma unroll
    for (int i = 0; i < 4; i++)
#pragma unroll
        for (int j = 0; j < 4; j++) acc2[i][j] = 0ull;

    float4 rA0 = reinterpret_cast<const float4*>(g_agg + (size_t)gr0 * FF)[k40];
    float4 rA1 = reinterpret_cast<const float4*>(g_agg + (size_t)gr1 * FF)[k41];
    float4 rH0 = reinterpret_cast<const float4*>(hin + (size_t)gr0 * FF)[k40];
    float4 rH1 = reinterpret_cast<const float4*>(hin + (size_t)gr1 * FF)[k41];

#pragma unroll
    for (int ck = 0; ck < 4; ck++) {
        const int kc = ck * 32;
        __syncthreads();
        reinterpret_cast<float4*>(sA + r0s * APITCH)[k40] = rA0;
        reinterpret_cast<float4*>(sA + r1s * APITCH)[k41] = rA1;
        reinterpret_cast<float4*>(sH + r0s * APITCH)[k40] = rH0;
        reinterpret_cast<float4*>(sH + r1s * APITCH)[k41] = rH1;
        __syncthreads();
        if (ck < 3) {
            const int kn = kc + 32;
            rA0 = reinterpret_cast<const float4*>(g_agg + (size_t)gr0 * FF + kn)[k40];
            rA1 = reinterpret_cast<const float4*>(g_agg + (size_t)gr1 * FF + kn)[k41];
            rH0 = reinterpret_cast<const float4*>(hin + (size_t)gr0 * FF + kn)[k40];
            rH1 = reinterpret_cast<const float4*>(hin + (size_t)gr1 * FF + kn)[k41];
        }
#pragma unroll
        for (int k = 0; k < 32; k++) {
            const float* wrow_l = sWl + (kc + k) * WPITCH;
            const float* wrow_r = sWr + (kc + k) * WPITCH;
            longlong2 wlA = *reinterpret_cast<const longlong2*>(wrow_l + cA);
            longlong2 wlB = *reinterpret_cast<const longlong2*>(wrow_l + cB);
            longlong2 wrA = *reinterpret_cast<const longlong2*>(wrow_r + cA);
            longlong2 wrB = *reinterpret_cast<const longlong2*>(wrow_r + cB);
#pragma unroll
            for (int i = 0; i < 4; i++) {
                float a = sA[(r0 + i) * APITCH + k];
                float h = sH[(r0 + i) * APITCH + k];
                unsigned long long aa = pk2(a, a);
                unsigned long long hh = pk2(h, h);
                ffma2(acc2[i][0], aa, (unsigned long long)wlA.x);
                ffma2(acc2[i][0], hh, (unsigned long long)wrA.x);
                ffma2(acc2[i][1], aa, (unsigned long long)wlA.y);
                ffma2(acc2[i][1], hh, (unsigned long long)wrA.y);
                ffma2(acc2[i][2], aa, (unsigned long long)wlB.x);
                ffma2(acc2[i][2], hh, (unsigned long long)wrB.x);
                ffma2(acc2[i][3], aa, (unsigned long long)wlB.y);
                ffma2(acc2[i][3], hh, (unsigned long long)wrB.y);
            }
        }
    }

    float4 b0 = *reinterpret_cast<const float4*>(blp + cA);
    float4 b1v = *reinterpret_cast<const float4*>(blp + cB);
#pragma unroll
    for (int i = 0; i < 4; i++) {
        int gr = row0 + r0 + i;
        if (gr < NN) {
            float4 o0, o1;
            upk2(o0.x, o0.y, acc2[i][0]);
            upk2(o0.z, o0.w, acc2[i][1]);
            upk2(o1.x, o1.y, acc2[i][2]);
            upk2(o1.z, o1.w, acc2[i][3]);
            o0.x += b0.x; o0.y += b0.y; o0.z += b0.z; o0.w += b0.w;
            o1.x += b1v.x; o1.y += b1v.y; o1.z += b1v.z; o1.w += b1v.w;
            *reinterpret_cast<float4*>(hout + (size_t)gr * FF + cA) = o0;
            *reinterpret_cast<float4*>(hout + (size_t)gr * FF + cB) = o1;
        }
    }
}

// ---- global max pool over each graph segment; one block per graph ----
__global__ void gs_pool_kernel() {
    int g = blockIdx.x;
    int s = g_start[g], e = g_start[g + 1];
    int t = threadIdx.x;            // 0..383
    int l = t >> 7, c = t & 127;
    const float* f = (l == 0) ? g_f1 : (l == 1) ? g_f2 : g_f3;
    float m = -3.402823466e38f;
    int i = s;
    for (; i + 4 <= e; i += 4) {
        float v0 = f[(size_t)(i + 0) * FF + c];
        float v1 = f[(size_t)(i + 1) * FF + c];
        float v2 = f[(size_t)(i + 2) * FF + c];
        float v3 = f[(size_t)(i + 3) * FF + c];
        m = fmaxf(m, fmaxf(fmaxf(v0, v1), fmaxf(v2, v3)));
    }
    for (; i < e; i++) m = fmaxf(m, f[(size_t)i * FF + c]);
    g_pool[g * (LL * FF) + t] = m;
}

// ---- MLP layer 1: z = relu(pool @ W1^T + b1) ----
__global__ void gs_mlp1_kernel(const float* __restrict__ b1) {
    __shared__ float sp[LL * FF];
    int g = blockIdx.x, t = threadIdx.x;   // 128 threads
    for (int i = t; i < LL * FF; i += FF) sp[i] = g_pool[g * (LL * FF) + i];
    __syncthreads();
    float acc = b1[t];
#pragma unroll 8
    for (int j = 0; j < LL * FF; j++) acc += sp[j] * g_W1T[j * FF + t];
    g_z[g * FF + t] = fmaxf(acc, 0.f);
}

// ---- MLP layer 2: out = z @ W2^T + b2 ----
__global__ void gs_mlp2_kernel(const float* __restrict__ W2,
                               const float* __restrict__ b2,
                               float* __restrict__ out) {
    __shared__ float sz[FF];
    int g = blockIdx.x, t = threadIdx.x;   // 128 threads
    sz[t] = g_z[g * FF + t];
    __syncthreads();
    if (t < TT) {
        float acc = b2[t];
#pragma unroll
        for (int c = 0; c < FF; c++) acc += sz[c] * W2[t * FF + c];
        out[g * TT + t] = acc;
    }
}

extern "C" void kernel_launch(void* const* d_in, const int* in_sizes, int n_in,
                              void* d_out, int out_size) {
    const float* x     = (const float*)d_in[0];
    const void*  ei    = d_in[1];
    const void*  batch = d_in[2];
    const float* Wl    = (const float*)d_in[3];
    const float* bl    = (const float*)d_in[4];
    const float* Wr    = (const float*)d_in[5];
    const float* W1    = (const float*)d_in[6];
    const float* b1    = (const float*)d_in[7];
    const float* W2    = (const float*)d_in[8];
    const float* b2    = (const float*)d_in[9];
    float* out = (float*)d_out;

    size_t smem = (size_t)(FF * WPITCH * 2 + BRF * APITCH * 2) * sizeof(float);
    cudaFuncSetAttribute(gs_gemm_kernel,
                         cudaFuncAttributeMaxDynamicSharedMemorySize, (int)smem);

    gs_init_kernel<<<(NN + 255) / 256, 256>>>(Wl, Wr, W1);
    gs_detect_kernel<<<1, 128>>>((const int*)ei);
    gs_convert_count_kernel<<<(EE + 255) / 256, 256>>>(ei);
    gs_scan1_kernel<<<SB, 256>>>();
    gs_scan2_kernel<<<1, SB>>>();
    gs_scan3_kernel<<<SB, 256>>>();
    gs_fill_kernel<<<(EE + 255) / 256, 256>>>();
    gs_bounds_kernel<<<(GG + 32) / 32, 32>>>(batch);

    void *p_f1, *p_f2, *p_f3, *p_wlt, *p_wrt;
    cudaGetSymbolAddress(&p_f1, g_f1);
    cudaGetSymbolAddress(&p_f2, g_f2);
    cudaGetSymbolAddress(&p_f3, g_f3);
    cudaGetSymbolAddress(&p_wlt, g_WlT);
    cudaGetSymbolAddress(&p_wrt, g_WrT);
    float* fbuf_sel[3] = {(float*)p_f1, (float*)p_f2, (float*)p_f3};

    const float* hin = x;
    for (int l = 0; l < LL; l++) {
        gs_gather_kernel<<<(NN * 32 + 255) / 256, 256>>>(hin);
        gs_gemm_kernel<<<(NN + BRF - 1) / BRF, 512, smem>>>(
            hin,
            (const float*)p_wlt + (size_t)l * FF * FF, bl + l * FF,
            (const float*)p_wrt + (size_t)l * FF * FF, fbuf_sel[l]);
        hin = fbuf_sel[l];
    }

    gs_pool_kernel<<<GG, LL * FF>>>();
    gs_mlp1_kernel<<<GG, FF>>>(b1);
    gs_mlp2_kernel<<<GG, FF>>>(W2, b2, out);
}

// round 16
// speedup vs baseline: 2.3329x; 1.0203x over previous
#include <cuda_runtime.h>
#include <cstdint>

#define NN 50000
#define EE 800000
#define FF 128
#define LL 3
#define GG 256
#define TT 10

#define BRF 128          // rows per GEMM block
#define KCH 64           // k-chunk
#define APITCH 68        // KCH + 4
#define WPITCH 132

#define SB 64            // scan blocks
#define SCH ((NN + SB * 256 - 1) / (SB * 256))   // 4
#define SBLK (SCH * 256)                          // 1024

// ---- scratch (device globals; no allocation allowed) ----
__device__ float g_agg[NN * FF];
__device__ float g_f1[NN * FF];
__device__ float g_f2[NN * FF];
__device__ float g_f3[NN * FF];
__device__ float g_WlT[LL * FF * FF];
__device__ float g_WrT[LL * FF * FF];
__device__ float g_W1T[LL * FF * FF];   // [384][128]
__device__ int   g_start[GG + 1];
__device__ int   g_src[EE];
__device__ int   g_dst[EE];
__device__ int   g_csr[EE];
__device__ int   g_rowptr[NN + 1];
__device__ int   g_indeg[NN];
__device__ int   g_cursor[NN];
__device__ int   g_bsum[SB + 1];
__device__ int   g_idx64;

// ---- packed f32x2 helpers (FFMA2 — reachable only via PTX) ----
__device__ __forceinline__ unsigned long long pk2(float lo, float hi) {
    unsigned long long r;
    asm("mov.b64 %0, {%1, %2};" : "=l"(r) : "f"(lo), "f"(hi));
    return r;
}
__device__ __forceinline__ void upk2(float& lo, float& hi, unsigned long long v) {
    asm("mov.b64 {%0, %1}, %2;" : "=f"(lo), "=f"(hi) : "l"(v));
}
__device__ __forceinline__ void ffma2(unsigned long long& d,
                                      unsigned long long a, unsigned long long b) {
    asm("fma.rn.f32x2 %0, %1, %2, %0;" : "+l"(d) : "l"(a), "l"(b));
}

// ---- fused init: zero indeg + weight pre-transpose ----
__global__ void gs_init_kernel(const float* __restrict__ Wl,
                               const float* __restrict__ Wr,
                               const float* __restrict__ W1) {
    int idx = blockIdx.x * blockDim.x + threadIdx.x;
    if (idx < NN) g_indeg[idx] = 0;
    if (idx < LL * FF * FF) {
        int l = idx / (FF * FF), r = idx % (FF * FF);
        int o = r / FF, k = r % FF;
        g_WlT[l * FF * FF + k * FF + o] = Wl[idx];
        g_WrT[l * FF * FF + k * FF + o] = Wr[idx];
        int c = idx / (LL * FF), j = idx % (LL * FF);
        g_W1T[j * FF + c] = W1[idx];
    }
}

// ---- dtype detection (parallel): int64 edge_index has all-zero high words ----
__global__ void gs_detect_kernel(const int* __restrict__ ei32) {
    __shared__ int flag;
    if (threadIdx.x == 0) flag = 1;
    __syncthreads();
    if (ei32[2 * threadIdx.x + 1] != 0) flag = 0;
    __syncthreads();
    if (threadIdx.x == 0) g_idx64 = flag;
}

__global__ void gs_convert_count_kernel(const void* __restrict__ ei) {
    int e = blockIdx.x * blockDim.x + threadIdx.x;
    if (e >= EE) return;
    int s, d;
    if (g_idx64) {
        const long long* p = (const long long*)ei;
        s = (int)p[e]; d = (int)p[EE + e];
    } else {
        const int* p = (const int*)ei;
        s = p[e]; d = p[EE + e];
    }
    g_src[e] = s; g_dst[e] = d;
    atomicAdd(&g_indeg[d], 1);
}

// ---- multi-block scan ----
__global__ void gs_scan1_kernel() {
    __shared__ int ssum[256];
    const int t = threadIdx.x, b = blockIdx.x;
    int s = 0;
    int base = b * SBLK + t;
#pragma unroll
    for (int i = 0; i < SCH; i++) {
        int idx = base + i * 256;
        if (idx < NN) s += g_indeg[idx];
    }
    ssum[t] = s;
    __syncthreads();
    for (int off = 128; off > 0; off >>= 1) {
        if (t < off) ssum[t] += ssum[t + off];
        __syncthreads();
    }
    if (t == 0) g_bsum[b] = ssum[0];
}

__global__ void gs_scan2_kernel() {
    __shared__ int sv[SB];
    const int t = threadIdx.x;
    sv[t] = g_bsum[t];
    __syncthreads();
    for (int off = 1; off < SB; off <<= 1) {
        int v = (t >= off) ? sv[t - off] : 0;
        __syncthreads();
        sv[t] += v;
        __syncthreads();
    }
    g_bsum[t] = (t == 0) ? 0 : sv[t - 1];
    if (t == SB - 1) g_rowptr[NN] = sv[SB - 1];
}

__global__ void gs_scan3_kernel() {
    __shared__ int ssum[256];
    const int t = threadIdx.x, b = blockIdx.x;
    int vals[SCH];
    int s = 0;
    const int base = b * SBLK + t * SCH;
#pragma unroll
    for (int i = 0; i < SCH; i++) {
        int idx = base + i;
        vals[i] = (idx < NN) ? g_indeg[idx] : 0;
        s += vals[i];
    }
    ssum[t] = s;
    __syncthreads();
    for (int off = 1; off < 256; off <<= 1) {
        int v = (t >= off) ? ssum[t - off] : 0;
        __syncthreads();
        ssum[t] += v;
        __syncthreads();
    }
    int running = g_bsum[b] + ((t == 0) ? 0 : ssum[t - 1]);
#pragma unroll
    for (int i = 0; i < SCH; i++) {
        int idx = base + i;
        if (idx < NN) {
            g_rowptr[idx] = running;
            g_cursor[idx] = running;
            running += vals[i];
        }
    }
}

__global__ void gs_fill_kernel() {
    int e = blockIdx.x * blockDim.x + threadIdx.x;
    if (e >= EE) return;
    int pos = atomicAdd(&g_cursor[g_dst[e]], 1);
    g_csr[pos] = g_src[e];
}

__global__ void gs_bounds_kernel(const void* __restrict__ batch) {
    int g = blockIdx.x * blockDim.x + threadIdx.x;
    if (g > GG) return;
    int is64 = g_idx64;
    const long long* b64 = (const long long*)batch;
    const int* b32 = (const int*)batch;
    int lo = 0, hi = NN;
    while (lo < hi) {
        int mid = (lo + hi) >> 1;
        long long v = is64 ? b64[mid] : (long long)b32[mid];
        if (v < (long long)g) lo = mid + 1; else hi = mid;
    }
    g_start[g] = lo;
}

// ---- gather-mean aggregation: one warp per dst node, no atomics ----
__global__ void __launch_bounds__(256) gs_gather_kernel(const float* __restrict__ h) {
    int warp = (blockIdx.x * blockDim.x + threadIdx.x) >> 5;
    int lane = threadIdx.x & 31;
    if (warp >= NN) return;
    int s0 = g_rowptr[warp], s1 = g_rowptr[warp + 1];
    float4 acc = make_float4(0.f, 0.f, 0.f, 0.f);
    int j = s0;
    for (; j + 4 <= s1; j += 4) {
        int a = g_csr[j], b = g_csr[j + 1], c = g_csr[j + 2], d = g_csr[j + 3];
        float4 v0 = reinterpret_cast<const float4*>(h + (size_t)a * FF)[lane];
        float4 v1 = reinterpret_cast<const float4*>(h + (size_t)b * FF)[lane];
        float4 v2 = reinterpret_cast<const float4*>(h + (size_t)c * FF)[lane];
        float4 v3 = reinterpret_cast<const float4*>(h + (size_t)d * FF)[lane];
        acc.x += (v0.x + v1.x) + (v2.x + v3.x);
        acc.y += (v0.y + v1.y) + (v2.y + v3.y);
        acc.z += (v0.z + v1.z) + (v2.z + v3.z);
        acc.w += (v0.w + v1.w) + (v2.w + v3.w);
    }
    for (; j < s1; j++) {
        int s = g_csr[j];
        float4 v = reinterpret_cast<const float4*>(h + (size_t)s * FF)[lane];
        acc.x += v.x; acc.y += v.y; acc.z += v.z; acc.w += v.w;
    }
    float iv = (s1 > s0) ? 1.f / (float)(s1 - s0) : 0.f;
    acc.x *= iv; acc.y *= iv; acc.z *= iv; acc.w *= iv;
    reinterpret_cast<float4*>(g_agg + (size_t)warp * FF)[lane] = acc;
}

// ---- fused SAGE layer GEMM: FFMA2, K-chunk 64, register-prefetch ----
__global__ void __launch_bounds__(512) gs_gemm_kernel(
    const float* __restrict__ hin,
    const float* __restrict__ WlT, const float* __restrict__ blp,
    const float* __restrict__ WrT, float* __restrict__ hout)
{
    extern __shared__ float sm[];
    float* sWl = sm;                         // 128 x WPITCH
    float* sWr = sWl + FF * WPITCH;          // 128 x WPITCH
    float* sA  = sWr + FF * WPITCH;          // BRF x APITCH
    float* sH  = sA + BRF * APITCH;          // BRF x APITCH
    const int t = threadIdx.x;
    const int row0 = blockIdx.x * BRF;

    for (int i = t; i < FF * FF / 4; i += 512) {
        int k = i >> 5, c4 = i & 31;
        float4 wl = reinterpret_cast<const float4*>(WlT)[i];
        float4 wr = reinterpret_cast<const float4*>(WrT)[i];
        reinterpret_cast<float4*>(sWl + k * WPITCH)[c4] = wl;
        reinterpret_cast<float4*>(sWr + k * WPITCH)[c4] = wr;
    }

    // staging: 128 rows x 16 float4 per matrix per chunk; 4 float4/thread/matrix
    int rs[4], ks[4], grs[4];
#pragma unroll
    for (int j = 0; j < 4; j++) {
        int i = t + j * 512;
        rs[j] = i >> 4; ks[j] = i & 15;
        int gr = row0 + rs[j]; if (gr >= NN) gr = NN - 1;
        grs[j] = gr;
    }

    const int tc = t & 15, tr = t >> 4;
    const int cA = tc * 4, cB = 64 + tc * 4, r0 = tr * 4;

    unsigned long long acc2[4][4];
#pragma unroll
    for (int i = 0; i < 4; i++)
#pragma unroll
        for (int j = 0; j < 4; j++) acc2[i][j] = 0ull;

    // prefetch chunk 0
    float4 pA[4], pH[4];
#pragma unroll
    for (int j = 0; j < 4; j++) {
        pA[j] = reinterpret_cast<const float4*>(g_agg + (size_t)grs[j] * FF)[ks[j]];
        pH[j] = reinterpret_cast<const float4*>(hin + (size_t)grs[j] * FF)[ks[j]];
    }

#pragma unroll
    for (int ck = 0; ck < 2; ck++) {
        const int kc = ck * KCH;
        __syncthreads();   // WAR on sA/sH
#pragma unroll
        for (int j = 0; j < 4; j++) {
            reinterpret_cast<float4*>(sA + rs[j] * APITCH)[ks[j]] = pA[j];
            reinterpret_cast<float4*>(sH + rs[j] * APITCH)[ks[j]] = pH[j];
        }
        __syncthreads();
        if (ck == 0) {     // prefetch chunk 1; hidden under 64-k compute
#pragma unroll
            for (int j = 0; j < 4; j++) {
                pA[j] = reinterpret_cast<const float4*>(
                    g_agg + (size_t)grs[j] * FF + KCH)[ks[j]];
                pH[j] = reinterpret_cast<const float4*>(
                    hin + (size_t)grs[j] * FF + KCH)[ks[j]];
            }
        }
#pragma unroll
        for (int k = 0; k < KCH; k++) {
            const float* wrow_l = sWl + (kc + k) * WPITCH;
            const float* wrow_r = sWr + (kc + k) * WPITCH;
            longlong2 wlA = *reinterpret_cast<const longlong2*>(wrow_l + cA);
            longlong2 wlB = *reinterpret_cast<const longlong2*>(wrow_l + cB);
            longlong2 wrA = *reinterpret_cast<const longlong2*>(wrow_r + cA);
            longlong2 wrB = *reinterpret_cast<const longlong2*>(wrow_r + cB);
#pragma unroll
            for (int i = 0; i < 4; i++) {
                float a = sA[(r0 + i) * APITCH + k];
                float h = sH[(r0 + i) * APITCH + k];
                unsigned long long aa = pk2(a, a);
                unsigned long long hh = pk2(h, h);
                ffma2(acc2[i][0], aa, (unsigned long long)wlA.x);
                ffma2(acc2[i][0], hh, (unsigned long long)wrA.x);
                ffma2(acc2[i][1], aa, (unsigned long long)wlA.y);
                ffma2(acc2[i][1], hh, (unsigned long long)wrA.y);
                ffma2(acc2[i][2], aa, (unsigned long long)wlB.x);
                ffma2(acc2[i][2], hh, (unsigned long long)wrB.x);
                ffma2(acc2[i][3], aa, (unsigned long long)wlB.y);
                ffma2(acc2[i][3], hh, (unsigned long long)wrB.y);
            }
        }
    }

    float4 b0 = *reinterpret_cast<const float4*>(blp + cA);
    float4 b1v = *reinterpret_cast<const float4*>(blp + cB);
#pragma unroll
    for (int i = 0; i < 4; i++) {
        int gr = row0 + r0 + i;
        if (gr < NN) {
            float4 o0, o1;
            upk2(o0.x, o0.y, acc2[i][0]);
            upk2(o0.z, o0.w, acc2[i][1]);
            upk2(o1.x, o1.y, acc2[i][2]);
            upk2(o1.z, o1.w, acc2[i][3]);
            o0.x += b0.x; o0.y += b0.y; o0.z += b0.z; o0.w += b0.w;
            o1.x += b1v.x; o1.y += b1v.y; o1.z += b1v.z; o1.w += b1v.w;
            *reinterpret_cast<float4*>(hout + (size_t)gr * FF + cA) = o0;
            *reinterpret_cast<float4*>(hout + (size_t)gr * FF + cB) = o1;
        }
    }
}

// ---- fused tail: global-max-pool + MLP1(relu) + MLP2, one block per graph ----
__global__ void __launch_bounds__(LL * FF) gs_tail_kernel(
    const float* __restrict__ b1, const float* __restrict__ W2,
    const float* __restrict__ b2, float* __restrict__ out)
{
    __shared__ float sp[LL * FF];
    __shared__ float sz[FF];
    int g = blockIdx.x;
    int s = g_start[g], e = g_start[g + 1];
    int t = threadIdx.x;            // 0..383
    int l = t >> 7, c = t & 127;
    const float* f = (l == 0) ? g_f1 : (l == 1) ? g_f2 : g_f3;
    float m = -3.402823466e38f;
    int i = s;
    for (; i + 4 <= e; i += 4) {
        float v0 = f[(size_t)(i + 0) * FF + c];
        float v1 = f[(size_t)(i + 1) * FF + c];
        float v2 = f[(size_t)(i + 2) * FF + c];
        float v3 = f[(size_t)(i + 3) * FF + c];
        m = fmaxf(m, fmaxf(fmaxf(v0, v1), fmaxf(v2, v3)));
    }
    for (; i < e; i++) m = fmaxf(m, f[(size_t)i * FF + c]);
    sp[t] = m;
    __syncthreads();
    if (t < FF) {
        float acc = b1[t];
#pragma unroll 8
        for (int j = 0; j < LL * FF; j++) acc += sp[j] * g_W1T[j * FF + t];
        sz[t] = fmaxf(acc, 0.f);
    }
    __syncthreads();
    if (t < TT) {
        float acc = b2[t];
#pragma unroll
        for (int c2 = 0; c2 < FF; c2++) acc += sz[c2] * W2[t * FF + c2];
        out[g * TT + t] = acc;
    }
}

extern "C" void kernel_launch(void* const* d_in, const int* in_sizes, int n_in,
                              void* d_out, int out_size) {
    const float* x     = (const float*)d_in[0];
    const void*  ei    = d_in[1];
    const void*  batch = d_in[2];
    const float* Wl    = (const float*)d_in[3];
    const float* bl    = (const float*)d_in[4];
    const float* Wr    = (const float*)d_in[5];
    const float* W1    = (const float*)d_in[6];
    const float* b1    = (const float*)d_in[7];
    const float* W2    = (const float*)d_in[8];
    const float* b2    = (const float*)d_in[9];
    float* out = (float*)d_out;

    size_t smem = (size_t)(FF * WPITCH * 2 + BRF * APITCH * 2) * sizeof(float);
    cudaFuncSetAttribute(gs_gemm_kernel,
                         cudaFuncAttributeMaxDynamicSharedMemorySize, (int)smem);

    gs_init_kernel<<<(NN + 255) / 256, 256>>>(Wl, Wr, W1);
    gs_detect_kernel<<<1, 128>>>((const int*)ei);
    gs_convert_count_kernel<<<(EE + 255) / 256, 256>>>(ei);
    gs_scan1_kernel<<<SB, 256>>>();
    gs_scan2_kernel<<<1, SB>>>();
    gs_scan3_kernel<<<SB, 256>>>();
    gs_fill_kernel<<<(EE + 255) / 256, 256>>>();
    gs_bounds_kernel<<<(GG + 32) / 32, 32>>>(batch);

    void *p_f1, *p_f2, *p_f3, *p_wlt, *p_wrt;
    cudaGetSymbolAddress(&p_f1, g_f1);
    cudaGetSymbolAddress(&p_f2, g_f2);
    cudaGetSymbolAddress(&p_f3, g_f3);
    cudaGetSymbolAddress(&p_wlt, g_WlT);
    cudaGetSymbolAddress(&p_wrt, g_WrT);
    float* fbuf_sel[3] = {(float*)p_f1, (float*)p_f2, (float*)p_f3};

    const float* hin = x;
    for (int l = 0; l < LL; l++) {
        gs_gather_kernel<<<(NN * 32 + 255) / 256, 256>>>(hin);
        gs_gemm_kernel<<<(NN + BRF - 1) / BRF, 512, smem>>>(
            hin,
            (const float*)p_wlt + (size_t)l * FF * FF, bl + l * FF,
            (const float*)p_wrt + (size_t)l * FF * FF, fbuf_sel[l]);
        hin = fbuf_sel[l];
    }

    gs_tail_kernel<<<GG, LL * FF>>>(b1, W2, b2, out);
}